// round 1
// baseline (speedup 1.0000x reference)
#include <cuda_runtime.h>
#include <cuda_bf16.h>

#define G 64
#define T 8192
#define E 64
#define CHUNKS 16                 // blocks per group
#define TPB 256                   // 8 warps
#define TOK_PER_BLOCK (T / CHUNKS) // 512

// Global scratch (no allocations allowed)
__device__ float g_probsum[G * E];
__device__ int   g_count[G * E];
__device__ float g_z;

__global__ void init_kernel() {
    int i = blockIdx.x * blockDim.x + threadIdx.x;
    if (i < G * E) { g_probsum[i] = 0.f; g_count[i] = 0; }
    if (i == 0) g_z = 0.f;
}

__global__ __launch_bounds__(TPB) void router_main(const float* __restrict__ logits) {
    __shared__ float s_prob[E];
    __shared__ int   s_cnt[E];
    __shared__ float s_z[TPB / 32];

    const int tid  = threadIdx.x;
    if (tid < E) { s_prob[tid] = 0.f; s_cnt[tid] = 0; }
    __syncthreads();

    const int g     = blockIdx.x / CHUNKS;
    const int chunk = blockIdx.x % CHUNKS;
    const int t0    = chunk * TOK_PER_BLOCK;
    const int wid   = tid >> 5;
    const int lane  = tid & 31;
    const int hl    = lane & 15;   // lane within half-warp; half-warp owns one token

    float acc0 = 0.f, acc1 = 0.f, acc2 = 0.f, acc3 = 0.f; // prob sums for experts hl*4..hl*4+3
    float zacc = 0.f;

    const float4* base = reinterpret_cast<const float4*>(logits + ((size_t)g * T + t0) * E);

    // Each warp iteration consumes 2 tokens (lanes 0-15 -> token 2i, lanes 16-31 -> token 2i+1)
    for (int i = wid; i < TOK_PER_BLOCK / 2; i += TPB / 32) {
        const float4 v = base[(size_t)i * 32 + lane];

        // local max + argmax (lowest index wins ties)
        float m = v.x; int ae = hl * 4;
        if (v.y > m) { m = v.y; ae = hl * 4 + 1; }
        if (v.z > m) { m = v.z; ae = hl * 4 + 2; }
        if (v.w > m) { m = v.w; ae = hl * 4 + 3; }
        #pragma unroll
        for (int o = 8; o >= 1; o >>= 1) {       // xor with <16 stays inside half-warp
            float mo = __shfl_xor_sync(0xffffffffu, m, o);
            int   io = __shfl_xor_sync(0xffffffffu, ae, o);
            if (mo > m || (mo == m && io < ae)) { m = mo; ae = io; }
        }

        float e0 = __expf(v.x - m), e1 = __expf(v.y - m);
        float e2 = __expf(v.z - m), e3 = __expf(v.w - m);
        float s = e0 + e1 + e2 + e3;
        #pragma unroll
        for (int o = 8; o >= 1; o >>= 1)
            s += __shfl_xor_sync(0xffffffffu, s, o);

        float inv = __frcp_rn(s);
        acc0 += e0 * inv; acc1 += e1 * inv; acc2 += e2 * inv; acc3 += e3 * inv;

        if (hl == 0) {
            float lz = m + __logf(s);
            zacc += lz * lz;
            atomicAdd(&s_cnt[ae], 1);
        }
    }

    atomicAdd(&s_prob[hl * 4 + 0], acc0);
    atomicAdd(&s_prob[hl * 4 + 1], acc1);
    atomicAdd(&s_prob[hl * 4 + 2], acc2);
    atomicAdd(&s_prob[hl * 4 + 3], acc3);

    #pragma unroll
    for (int o = 16; o >= 1; o >>= 1)
        zacc += __shfl_xor_sync(0xffffffffu, zacc, o);
    if (lane == 0) s_z[wid] = zacc;
    __syncthreads();

    if (tid < E) {
        atomicAdd(&g_probsum[g * E + tid], s_prob[tid]);
        atomicAdd(&g_count[g * E + tid], s_cnt[tid]);
    }
    if (tid == 0) {
        float z = 0.f;
        #pragma unroll
        for (int w = 0; w < TPB / 32; w++) z += s_z[w];
        atomicAdd(&g_z, z);
    }
}

// one block of 512 threads (16 warps); each warp handles 4 groups
__global__ void finalize_kernel(const int* __restrict__ cap_ptr, float* __restrict__ out) {
    __shared__ float s_aux[16];
    const int tid = threadIdx.x, wid = tid >> 5, lane = tid & 31;
    const int cap = cap_ptr ? *cap_ptr : 160;

    float aux = 0.f;
    for (int g = wid; g < G; g += 16) {
        int c0 = g_count[g * E + lane];
        int c1 = g_count[g * E + lane + 32];
        int k0 = min(c0, cap), k1 = min(c1, cap);
        int ex = (c0 - k0) + (c1 - k1);
        #pragma unroll
        for (int o = 16; o >= 1; o >>= 1)
            ex += __shfl_xor_sync(0xffffffffu, ex, o);   // total dropped in group g
        float a0 = (float)k0 + ((lane == 0) ? (float)ex : 0.f); // dropped -> expert 0
        float contrib = a0 * g_probsum[g * E + lane]
                      + (float)k1 * g_probsum[g * E + lane + 32];
        #pragma unroll
        for (int o = 16; o >= 1; o >>= 1)
            contrib += __shfl_xor_sync(0xffffffffu, contrib, o);
        if (lane == 0) aux += contrib;
    }
    if (lane == 0) s_aux[wid] = aux;
    __syncthreads();

    if (tid == 0) {
        float S = 0.f;
        #pragma unroll
        for (int w = 0; w < 16; w++) S += s_aux[w];
        float z_loss  = g_z / ((float)G * (float)T);
        // aux = mean_{g,e}(tpe*rpe)*E^2 = (E/G) * S / T^2 ; E==G so factor is 1
        float aux_loss = S * ((float)E / (float)G) / ((float)T * (float)T);
        out[0] = 0.001f * z_loss + 0.001f * aux_loss;
    }
}

extern "C" void kernel_launch(void* const* d_in, const int* in_sizes, int n_in,
                              void* d_out, int out_size) {
    const float* logits = (const float*)d_in[0];
    const int* cap = (n_in >= 3) ? (const int*)d_in[2] : nullptr;
    float* out = (float*)d_out;

    init_kernel<<<(G * E + 255) / 256, 256>>>();
    router_main<<<G * CHUNKS, TPB>>>(logits);
    finalize_kernel<<<1, 512>>>(cap, out);
}

// round 2
// speedup vs baseline: 1.0426x; 1.0426x over previous
#include <cuda_runtime.h>
#include <cuda_bf16.h>

#define G 64
#define T 8192
#define E 64
#define CHUNKS 16                   // blocks per group
#define TPB 256                     // 8 warps
#define WARPS (TPB / 32)
#define TOK_PER_BLOCK (T / CHUNKS)  // 512
#define ITERS (TOK_PER_BLOCK / 2 / WARPS)  // 32 warp-iterations (2 tokens each)
#define UNROLL 4

// Global scratch (zero-initialized at module load; finalize re-zeroes each call)
__device__ float g_probsum[G * E];
__device__ int   g_count[G * E];
__device__ float g_z;

__global__ __launch_bounds__(TPB) void router_main(const float* __restrict__ logits) {
    __shared__ float s_prob[E];
    __shared__ int   s_cnt[E];
    __shared__ float s_z[WARPS];

    const int tid = threadIdx.x;
    if (tid < E) { s_prob[tid] = 0.f; s_cnt[tid] = 0; }
    __syncthreads();

    const int g     = blockIdx.x >> 4;      // / CHUNKS
    const int chunk = blockIdx.x & (CHUNKS - 1);
    const int wid   = tid >> 5;
    const int lane  = tid & 31;
    const int hl    = lane & 15;            // lane within half-warp; half-warp owns one token

    float acc0 = 0.f, acc1 = 0.f, acc2 = 0.f, acc3 = 0.f;
    float zacc = 0.f;

    const float4* base = reinterpret_cast<const float4*>(
        logits + ((size_t)g * T + (size_t)chunk * TOK_PER_BLOCK) * E);

    #pragma unroll 1
    for (int k = 0; k < ITERS; k += UNROLL) {
        // Batched independent loads: MLP_p1 = UNROLL (4 x 512B per warp in flight)
        float4 v[UNROLL];
        #pragma unroll
        for (int u = 0; u < UNROLL; u++)
            v[u] = base[((size_t)(k + u) * WARPS + wid) * 32 + lane];

        #pragma unroll
        for (int u = 0; u < UNROLL; u++) {
            const float4 x = v[u];

            // local max + argmax (lowest index wins ties)
            float m = x.x; int ae = hl * 4;
            if (x.y > m) { m = x.y; ae = hl * 4 + 1; }
            if (x.z > m) { m = x.z; ae = hl * 4 + 2; }
            if (x.w > m) { m = x.w; ae = hl * 4 + 3; }
            #pragma unroll
            for (int o = 8; o >= 1; o >>= 1) {   // xor < 16 stays within half-warp
                float mo = __shfl_xor_sync(0xffffffffu, m, o);
                int   io = __shfl_xor_sync(0xffffffffu, ae, o);
                if (mo > m || (mo == m && io < ae)) { m = mo; ae = io; }
            }

            float e0 = __expf(x.x - m), e1 = __expf(x.y - m);
            float e2 = __expf(x.z - m), e3 = __expf(x.w - m);
            float s = e0 + e1 + e2 + e3;
            #pragma unroll
            for (int o = 8; o >= 1; o >>= 1)
                s += __shfl_xor_sync(0xffffffffu, s, o);

            float inv = __frcp_rn(s);
            acc0 += e0 * inv; acc1 += e1 * inv; acc2 += e2 * inv; acc3 += e3 * inv;

            if (hl == 0) {
                float lz = m + __logf(s);
                zacc += lz * lz;
                atomicAdd(&s_cnt[ae], 1);
            }
        }
    }

    atomicAdd(&s_prob[hl * 4 + 0], acc0);
    atomicAdd(&s_prob[hl * 4 + 1], acc1);
    atomicAdd(&s_prob[hl * 4 + 2], acc2);
    atomicAdd(&s_prob[hl * 4 + 3], acc3);

    #pragma unroll
    for (int o = 16; o >= 1; o >>= 1)
        zacc += __shfl_xor_sync(0xffffffffu, zacc, o);
    if (lane == 0) s_z[wid] = zacc;
    __syncthreads();

    if (tid < E) {
        atomicAdd(&g_probsum[g * E + tid], s_prob[tid]);
        atomicAdd(&g_count[g * E + tid], s_cnt[tid]);
    }
    if (tid == 0) {
        float z = 0.f;
        #pragma unroll
        for (int w = 0; w < WARPS; w++) z += s_z[w];
        atomicAdd(&g_z, z);
    }
}

// One block of 512 threads (16 warps); each warp handles 4 groups.
// Also RESETS the global accumulators so the next graph replay starts clean.
__global__ void finalize_kernel(const int* __restrict__ cap_ptr, float* __restrict__ out) {
    __shared__ float s_aux[16];
    const int tid = threadIdx.x, wid = tid >> 5, lane = tid & 31;
    const int cap = cap_ptr ? *cap_ptr : 160;

    float aux = 0.f;
    for (int g = wid; g < G; g += 16) {
        int c0 = g_count[g * E + lane];
        int c1 = g_count[g * E + lane + 32];
        int k0 = min(c0, cap), k1 = min(c1, cap);
        int ex = (c0 - k0) + (c1 - k1);
        #pragma unroll
        for (int o = 16; o >= 1; o >>= 1)
            ex += __shfl_xor_sync(0xffffffffu, ex, o);   // total dropped in group g
        float a0 = (float)k0 + ((lane == 0) ? (float)ex : 0.f); // dropped -> expert 0
        float contrib = a0 * g_probsum[g * E + lane]
                      + (float)k1 * g_probsum[g * E + lane + 32];
        #pragma unroll
        for (int o = 16; o >= 1; o >>= 1)
            contrib += __shfl_xor_sync(0xffffffffu, contrib, o);
        if (lane == 0) aux += contrib;
    }
    if (lane == 0) s_aux[wid] = aux;
    __syncthreads();

    if (tid == 0) {
        float S = 0.f;
        #pragma unroll
        for (int w = 0; w < 16; w++) S += s_aux[w];
        float z_loss  = g_z / ((float)G * (float)T);
        // aux = mean_{g,e}(tpe*rpe)*E^2 = (E/G) * S / T^2
        float aux_loss = S * ((float)E / (float)G) / ((float)T * (float)T);
        out[0] = 0.001f * z_loss + 0.001f * aux_loss;
    }
    __syncthreads();

    // Reset accumulators for the next call (globals were read above).
    for (int i = tid; i < G * E; i += blockDim.x) {
        g_probsum[i] = 0.f;
        g_count[i] = 0;
    }
    if (tid == 0) g_z = 0.f;
}

extern "C" void kernel_launch(void* const* d_in, const int* in_sizes, int n_in,
                              void* d_out, int out_size) {
    const float* logits = (const float*)d_in[0];
    const int* cap = (n_in >= 3) ? (const int*)d_in[2] : nullptr;
    float* out = (float*)d_out;

    router_main<<<G * CHUNKS, TPB>>>(logits);
    finalize_kernel<<<1, 512>>>(cap, out);
}

// round 3
// speedup vs baseline: 1.4642x; 1.4044x over previous
#include <cuda_runtime.h>

#define G 64
#define T 8192
#define E 64
#define CHUNKS 8
#define NBLOCKS (G * CHUNKS)               // 512
#define TPB 256
#define WARPS (TPB / 32)
#define TOKS_BLOCK (T / CHUNKS)            // 1024
#define WITERS (TOKS_BLOCK / (WARPS * 4))  // 32 warp-iterations (4 tokens each)
#define UNROLL 2
#define LOG2E 1.4426950408889634f

// Global scratch (zero-initialized at module load; last block re-zeroes each call)
__device__ float        g_probsum[G * E];
__device__ float        g_cnt[G * E];
__device__ float        g_z;
__device__ unsigned int g_done;

__global__ __launch_bounds__(TPB, 4) void router_kernel(
    const float* __restrict__ logits,
    const int*   __restrict__ cap_ptr,
    float*       __restrict__ out)
{
    __shared__ float s_prob[E];
    __shared__ float s_cnt[E];
    __shared__ float s_z[WARPS];
    __shared__ float s_aux[WARPS];
    __shared__ unsigned int s_last;

    const int tid = threadIdx.x;
    if (tid < E) { s_prob[tid] = 0.f; s_cnt[tid] = 0.f; }
    __syncthreads();

    const int g     = blockIdx.x >> 3;            // / CHUNKS
    const int chunk = blockIdx.x & (CHUNKS - 1);
    const int wid   = tid >> 5;
    const int lane  = tid & 31;
    const int sl    = lane & 7;                   // lane within 8-lane segment
    // segment (lane>>3) owns one token per warp-iteration

    // Register accumulators: accP[j]<->expert sl*4+j, accP[4+j]<->expert 32+sl*4+j
    float accP[8] = {0.f,0.f,0.f,0.f,0.f,0.f,0.f,0.f};
    float accC[8] = {0.f,0.f,0.f,0.f,0.f,0.f,0.f,0.f};
    float zacc = 0.f;

    const float4* base = reinterpret_cast<const float4*>(
        logits + ((size_t)g * T + (size_t)chunk * TOKS_BLOCK) * E);
    const int lane_off = ((lane >> 3) << 4) + sl;  // seg*16 + sl

    #pragma unroll 1
    for (int it = 0; it < WITERS; it += UNROLL) {
        float4 va[UNROLL], vb[UNROLL];
        #pragma unroll
        for (int u = 0; u < UNROLL; u++) {
            const size_t off = (size_t)((it + u) * WARPS + wid) * 64;
            va[u] = base[off + lane_off];        // experts [4sl, 4sl+4)
            vb[u] = base[off + lane_off + 8];    // experts [32+4sl, 32+4sl+4)
        }
        #pragma unroll
        for (int u = 0; u < UNROLL; u++) {
            const float4 a = va[u], b = vb[u];

            // segment max (FMNMX tree + 3-stage shfl ladder, no predicates)
            float m = fmaxf(fmaxf(fmaxf(a.x, a.y), fmaxf(a.z, a.w)),
                            fmaxf(fmaxf(b.x, b.y), fmaxf(b.z, b.w)));
            m = fmaxf(m, __shfl_xor_sync(0xffffffffu, m, 1));
            m = fmaxf(m, __shfl_xor_sync(0xffffffffu, m, 2));
            m = fmaxf(m, __shfl_xor_sync(0xffffffffu, m, 4));

            // argmax counts via exact-equality with the propagated max
            accC[0] += (a.x == m) ? 1.f : 0.f;
            accC[1] += (a.y == m) ? 1.f : 0.f;
            accC[2] += (a.z == m) ? 1.f : 0.f;
            accC[3] += (a.w == m) ? 1.f : 0.f;
            accC[4] += (b.x == m) ? 1.f : 0.f;
            accC[5] += (b.y == m) ? 1.f : 0.f;
            accC[6] += (b.z == m) ? 1.f : 0.f;
            accC[7] += (b.w == m) ? 1.f : 0.f;

            // exp(x-m) = 2^(x*log2e - m*log2e): 1 FFMA + 1 MUFU per element
            const float ml = m * LOG2E;
            float e0 = exp2f(fmaf(a.x, LOG2E, -ml));
            float e1 = exp2f(fmaf(a.y, LOG2E, -ml));
            float e2 = exp2f(fmaf(a.z, LOG2E, -ml));
            float e3 = exp2f(fmaf(a.w, LOG2E, -ml));
            float e4 = exp2f(fmaf(b.x, LOG2E, -ml));
            float e5 = exp2f(fmaf(b.y, LOG2E, -ml));
            float e6 = exp2f(fmaf(b.z, LOG2E, -ml));
            float e7 = exp2f(fmaf(b.w, LOG2E, -ml));

            float s = ((e0 + e1) + (e2 + e3)) + ((e4 + e5) + (e6 + e7));
            s += __shfl_xor_sync(0xffffffffu, s, 1);
            s += __shfl_xor_sync(0xffffffffu, s, 2);
            s += __shfl_xor_sync(0xffffffffu, s, 4);

            const float inv = __fdividef(1.f, s);
            accP[0] = fmaf(e0, inv, accP[0]);
            accP[1] = fmaf(e1, inv, accP[1]);
            accP[2] = fmaf(e2, inv, accP[2]);
            accP[3] = fmaf(e3, inv, accP[3]);
            accP[4] = fmaf(e4, inv, accP[4]);
            accP[5] = fmaf(e5, inv, accP[5]);
            accP[6] = fmaf(e6, inv, accP[6]);
            accP[7] = fmaf(e7, inv, accP[7]);

            if (sl == 0) {                 // one lane per token: z-loss term
                const float lz = m + __logf(s);
                zacc = fmaf(lz, lz, zacc);
            }
        }
    }

    // reduce accumulators across the 4 segments (same expert <-> same sl)
    #pragma unroll
    for (int k = 0; k < 8; k++) {
        accP[k] += __shfl_xor_sync(0xffffffffu, accP[k], 8);
        accP[k] += __shfl_xor_sync(0xffffffffu, accP[k], 16);
        accC[k] += __shfl_xor_sync(0xffffffffu, accC[k], 8);
        accC[k] += __shfl_xor_sync(0xffffffffu, accC[k], 16);
    }
    if (lane < 8) {
        #pragma unroll
        for (int j = 0; j < 4; j++) {
            atomicAdd(&s_prob[sl * 4 + j],      accP[j]);
            atomicAdd(&s_prob[32 + sl * 4 + j], accP[4 + j]);
            atomicAdd(&s_cnt[sl * 4 + j],       accC[j]);
            atomicAdd(&s_cnt[32 + sl * 4 + j],  accC[4 + j]);
        }
    }
    zacc += __shfl_xor_sync(0xffffffffu, zacc, 8);
    zacc += __shfl_xor_sync(0xffffffffu, zacc, 16);
    if (lane == 0) s_z[wid] = zacc;
    __syncthreads();

    if (tid < E) {
        atomicAdd(&g_probsum[g * E + tid], s_prob[tid]);
        atomicAdd(&g_cnt[g * E + tid],     s_cnt[tid]);
    }
    if (tid == 0) {
        float z = 0.f;
        #pragma unroll
        for (int w = 0; w < WARPS; w++) z += s_z[w];
        atomicAdd(&g_z, z);
    }

    // ---- last block performs finalize + reset (no second launch) ----
    __threadfence();
    if (tid == 0)
        s_last = (atomicAdd(&g_done, 1u) == (unsigned)(NBLOCKS - 1)) ? 1u : 0u;
    __syncthreads();
    if (!s_last) return;
    __threadfence();

    const float capf = (float)(cap_ptr ? *cap_ptr : 160);
    float aux = 0.f;
    for (int gg = wid; gg < G; gg += WARPS) {
        const float c0 = g_cnt[gg * E + lane];
        const float c1 = g_cnt[gg * E + lane + 32];
        const float k0 = fminf(c0, capf), k1 = fminf(c1, capf);
        float ex = (c0 - k0) + (c1 - k1);        // dropped tokens in group gg
        #pragma unroll
        for (int o = 16; o >= 1; o >>= 1)
            ex += __shfl_xor_sync(0xffffffffu, ex, o);
        const float a0 = k0 + ((lane == 0) ? ex : 0.f);  // dropped -> expert 0
        float contrib = a0 * g_probsum[gg * E + lane]
                      + k1 * g_probsum[gg * E + lane + 32];
        #pragma unroll
        for (int o = 16; o >= 1; o >>= 1)
            contrib += __shfl_xor_sync(0xffffffffu, contrib, o);
        if (lane == 0) aux += contrib;
    }
    if (lane == 0) s_aux[wid] = aux;
    __syncthreads();

    if (tid == 0) {
        float S = 0.f;
        #pragma unroll
        for (int w = 0; w < WARPS; w++) S += s_aux[w];
        const float z_loss   = g_z / ((float)G * (float)T);
        const float aux_loss = S * ((float)E / (float)G) / ((float)T * (float)T);
        out[0] = 0.001f * (z_loss + aux_loss);
    }
    __syncthreads();   // all finalize reads complete before reset

    for (int i = tid; i < G * E; i += TPB) { g_probsum[i] = 0.f; g_cnt[i] = 0.f; }
    if (tid == 0) { g_z = 0.f; g_done = 0u; }
}

extern "C" void kernel_launch(void* const* d_in, const int* in_sizes, int n_in,
                              void* d_out, int out_size) {
    const float* logits = (const float*)d_in[0];
    const int* cap = (n_in >= 3) ? (const int*)d_in[2] : nullptr;
    float* out = (float*)d_out;

    router_kernel<<<NBLOCKS, TPB>>>(logits, cap, out);
}